// round 4
// baseline (speedup 1.0000x reference)
#include <cuda_runtime.h>
#include <cstdint>

#define N_ATOMS 4096
#define L_WORDS 65536
#define DD 10
#define KS 23
#define KSPLIT 4
#define KCHUNK (N_ATOMS / KSPLIT)   // 1024 columns per k-block

// ---------------- scratch (device globals; no allocation allowed) ----------
__device__ float g_xs[2][N_ATOMS * DD];              // GNN xs ping-pong
// hs packed f32x2, layout [k4][p][m/4] with k4 = m&3 (conflict-free float4 cols)
__device__ unsigned long long g_hs[4 * 5 * (N_ATOMS / 4)];
__device__ float g_pp[KSPLIT][N_ATOMS * DD];         // split-K partials of A@hs
__device__ float g_cnn[2][L_WORDS * DD];             // CNN ping-pong
__device__ float g_comp[DD];
__device__ float g_hatt[DD];
__device__ float g_part[512 * DD];                   // attention partial sums

// ---------------- f32x2 helpers (sm_103a packed fp32) -----------------------
__device__ __forceinline__ unsigned long long pack2(float x, float y) {
    unsigned long long r;
    asm("mov.b64 %0, {%1, %2};" : "=l"(r) : "f"(x), "f"(y));
    return r;
}
__device__ __forceinline__ void unpack2(unsigned long long v, float& x, float& y) {
    asm("mov.b64 {%0, %1}, %2;" : "=f"(x), "=f"(y) : "l"(v));
}
__device__ __forceinline__ void fma2(unsigned long long& d, unsigned long long a,
                                     unsigned long long b) {
    asm("fma.rn.f32x2 %0, %1, %2, %0;" : "+l"(d) : "l"(a), "l"(b));
}

// ---------------- gathers ---------------------------------------------------
__global__ void k_gather_fp(const int* __restrict__ fp, const float* __restrict__ emb) {
    int i = blockIdx.x * blockDim.x + threadIdx.x;
    if (i < N_ATOMS * DD) {
        int n = i / DD, d = i - n * DD;
        g_xs[0][i] = emb[(size_t)fp[n] * DD + d];
    }
}
__global__ void k_gather_w(const int* __restrict__ wd, const float* __restrict__ emb) {
    int i = blockIdx.x * blockDim.x + threadIdx.x;
    if (i < L_WORDS * DD) {
        int n = i / DD, d = i - n * DD;
        g_cnn[0][i] = emb[(size_t)wd[n] * DD + d];
    }
}

// ---------------- GNN: (optional combine) + hs = relu(xs @ W^T + b) ---------
__global__ void k_hs(int inbuf, int outbuf, int addp,
                     const float* __restrict__ Wg, const float* __restrict__ bg) {
    int m = blockIdx.x * blockDim.x + threadIdx.x;
    if (m >= N_ATOMS) return;
    float x[DD];
#pragma unroll
    for (int c = 0; c < DD; c++) {
        float v = g_xs[inbuf][m * DD + c];
        if (addp) {
#pragma unroll
            for (int kb = 0; kb < KSPLIT; kb++) v += g_pp[kb][m * DD + c];
            g_xs[outbuf][m * DD + c] = v;
        }
        x[c] = v;
    }
    int k4 = m & 3, base = m >> 2;
#pragma unroll
    for (int p = 0; p < 5; p++) {
        float h0 = bg[2 * p], h1 = bg[2 * p + 1];
#pragma unroll
        for (int c = 0; c < DD; c++) {
            h0 = fmaf(x[c], Wg[(2 * p) * DD + c], h0);
            h1 = fmaf(x[c], Wg[(2 * p + 1) * DD + c], h1);
        }
        g_hs[(k4 * 5 + p) * (N_ATOMS / 4) + base] = pack2(fmaxf(h0, 0.f), fmaxf(h1, 0.f));
    }
}

// ---------------- GNN: P[kb] = A[:, kb-chunk] @ hs[kb-chunk] ----------------
// Grid (256 row-blocks, 4 k-blocks) x 256 threads. Warp owns 2 rows; lane does
// 4 consecutive k via LDG.128 + prefetch. hs chunk (40KB) in smem -> 4 CTA/SM.
__global__ void __launch_bounds__(256, 4) k_gnn(const float* __restrict__ A) {
    extern __shared__ unsigned long long sh[];  // 20*256 ull = 40KB
    int tid = threadIdx.x;
    int kb = blockIdx.y;
    for (int i = tid; i < 20 * (KCHUNK / 4); i += 256) {
        int kp = i / (KCHUNK / 4), j = i % (KCHUNK / 4);
        sh[i] = g_hs[kp * (N_ATOMS / 4) + kb * (KCHUNK / 4) + j];
    }
    __syncthreads();

    int warp = tid >> 5, lane = tid & 31;
    int row0 = blockIdx.x * 16 + warp * 2;
    float* pout = g_pp[kb];

    const float4* A0 = (const float4*)(A + (size_t)(row0 + 0) * N_ATOMS) + kb * (KCHUNK / 4);
    const float4* A1 = (const float4*)(A + (size_t)(row0 + 1) * N_ATOMS) + kb * (KCHUNK / 4);

    unsigned long long acc[2][5];
#pragma unroll
    for (int r = 0; r < 2; r++)
#pragma unroll
        for (int p = 0; p < 5; p++) acc[r][p] = 0ull;

    float4 a0 = A0[lane], a1 = A1[lane];

    for (int it = 0; it < KCHUNK / 128; it++) {
        int q0 = it * 32;
        float4 n0, n1;
        if (it + 1 < KCHUNK / 128) {
            n0 = A0[q0 + 32 + lane];
            n1 = A1[q0 + 32 + lane];
        }
#pragma unroll
        for (int k = 0; k < 4; k++) {
            unsigned long long h[5];
#pragma unroll
            for (int p = 0; p < 5; p++)
                h[p] = sh[(k * 5 + p) * (KCHUNK / 4) + q0 + lane];
            float av0 = (k == 0) ? a0.x : (k == 1) ? a0.y : (k == 2) ? a0.z : a0.w;
            float av1 = (k == 0) ? a1.x : (k == 1) ? a1.y : (k == 2) ? a1.z : a1.w;
            unsigned long long v0 = pack2(av0, av0), v1 = pack2(av1, av1);
#pragma unroll
            for (int p = 0; p < 5; p++) {
                fma2(acc[0][p], v0, h[p]);
                fma2(acc[1][p], v1, h[p]);
            }
        }
        a0 = n0; a1 = n1;
    }

    float f[2][DD];
#pragma unroll
    for (int r = 0; r < 2; r++)
#pragma unroll
        for (int p = 0; p < 5; p++) unpack2(acc[r][p], f[r][2 * p], f[r][2 * p + 1]);
#pragma unroll
    for (int r = 0; r < 2; r++)
#pragma unroll
        for (int d = 0; d < DD; d++)
#pragma unroll
            for (int o = 16; o > 0; o >>= 1)
                f[r][d] += __shfl_down_sync(0xffffffffu, f[r][d], o);

    if (lane == 0) {
#pragma unroll
        for (int r = 0; r < 2; r++) {
            int row = row0 + r;
#pragma unroll
            for (int d = 0; d < DD; d++)
                pout[row * DD + d] = f[r][d];
        }
    }
}

// ---------------- CNN layer (layers 0 and 1) ---------------------------------
// out[l,j] = relu(b + sum_{dl=0..22, c=0..9} in[l-11+dl, c] * W[dl, 11+c-j])
// 128 threads, 1 row/thread -> 128 rows/block, 512 blocks.
#define CTHREADS 128
__global__ void k_cnn(int buf, const float* __restrict__ Wc, const float* __restrict__ bc,
                      int layer) {
    __shared__ float sIn[(CTHREADS + 22) * 11];
    __shared__ unsigned long long sW[KS * 50];      // [dl][c][p] f32x2 over j-pairs
    int tid = threadIdx.x;
    const float* in = g_cnn[buf];
    float* out = g_cnn[buf ^ 1];
    const float* W = Wc + layer * KS * KS;
    float bias = bc[layer];

    for (int i = tid; i < KS * 50; i += CTHREADS) {
        int dl = i / 50, rem = i % 50, c = rem / 5, p = rem % 5;
        float w0 = W[dl * KS + 11 + c - 2 * p];
        float w1 = W[dl * KS + 11 + c - 2 * p - 1];
        sW[i] = pack2(w0, w1);
    }
    int base = blockIdx.x * CTHREADS - 11;
    for (int i = tid; i < (CTHREADS + 22) * DD; i += CTHREADS) {
        int rr = i / DD, c = i - rr * DD;
        int g = base + rr;
        sIn[rr * 11 + c] = (g >= 0 && g < L_WORDS) ? in[g * DD + c] : 0.f;
    }
    __syncthreads();

    unsigned long long b2 = pack2(bias, bias);
    unsigned long long acc[5];
#pragma unroll
    for (int p = 0; p < 5; p++) acc[p] = b2;

#pragma unroll 1
    for (int dl = 0; dl < KS; dl++) {
#pragma unroll
        for (int c = 0; c < DD; c++) {
            float x = sIn[(tid + dl) * 11 + c];
            unsigned long long x2 = pack2(x, x);
#pragma unroll
            for (int p = 0; p < 5; p++) fma2(acc[p], x2, sW[dl * 50 + c * 5 + p]);
        }
    }

    int grow = blockIdx.x * CTHREADS + tid;
#pragma unroll
    for (int p = 0; p < 5; p++) {
        float v0, v1;
        unpack2(acc[p], v0, v1);
        out[grow * DD + 2 * p] = fmaxf(v0, 0.f);
        out[grow * DD + 2 * p + 1] = fmaxf(v1, 0.f);
    }
}

// ---------------- CNN layer 2 fused with attention ---------------------------
// Computes conv output row in registers, then hs_p = relu(x@Wat^T+bat),
// w = tanh(h . hs_p), accumulates w*hs_p into per-block partial sums.
__global__ void k_cnn_att(int buf, const float* __restrict__ Wc, const float* __restrict__ bc,
                          const float* __restrict__ Wat, const float* __restrict__ bat) {
    __shared__ float sIn[(CTHREADS + 22) * 11];
    __shared__ unsigned long long sW[KS * 50];
    __shared__ float sWat[DD * DD], sb[DD], shv[DD];
    __shared__ float red[CTHREADS * DD];
    int tid = threadIdx.x;
    const float* in = g_cnn[buf];
    const float* W = Wc + 2 * KS * KS;
    float bias = bc[2];

    for (int i = tid; i < KS * 50; i += CTHREADS) {
        int dl = i / 50, rem = i % 50, c = rem / 5, p = rem % 5;
        float w0 = W[dl * KS + 11 + c - 2 * p];
        float w1 = W[dl * KS + 11 + c - 2 * p - 1];
        sW[i] = pack2(w0, w1);
    }
    if (tid < DD * DD) sWat[tid] = Wat[tid];
    if (tid < DD) { sb[tid] = bat[tid]; shv[tid] = g_hatt[tid]; }
    int base = blockIdx.x * CTHREADS - 11;
    for (int i = tid; i < (CTHREADS + 22) * DD; i += CTHREADS) {
        int rr = i / DD, c = i - rr * DD;
        int g = base + rr;
        sIn[rr * 11 + c] = (g >= 0 && g < L_WORDS) ? in[g * DD + c] : 0.f;
    }
    __syncthreads();

    unsigned long long b2 = pack2(bias, bias);
    unsigned long long acc[5];
#pragma unroll
    for (int p = 0; p < 5; p++) acc[p] = b2;
#pragma unroll 1
    for (int dl = 0; dl < KS; dl++) {
#pragma unroll
        for (int c = 0; c < DD; c++) {
            float xv = sIn[(tid + dl) * 11 + c];
            unsigned long long x2 = pack2(xv, xv);
#pragma unroll
            for (int p = 0; p < 5; p++) fma2(acc[p], x2, sW[dl * 50 + c * 5 + p]);
        }
    }
    float x[DD];
#pragma unroll
    for (int p = 0; p < 5; p++) {
        float v0, v1;
        unpack2(acc[p], v0, v1);
        x[2 * p] = fmaxf(v0, 0.f);
        x[2 * p + 1] = fmaxf(v1, 0.f);
    }

    // attention
    float hp[DD], wl = 0.f;
#pragma unroll
    for (int t = 0; t < DD; t++) {
        float v = sb[t];
#pragma unroll
        for (int c = 0; c < DD; c++) v = fmaf(x[c], sWat[t * DD + c], v);
        v = fmaxf(v, 0.f);
        hp[t] = v;
        wl = fmaf(shv[t], v, wl);
    }
    wl = tanhf(wl);
#pragma unroll
    for (int d = 0; d < DD; d++) red[tid * DD + d] = wl * hp[d];
    __syncthreads();
    for (int s = CTHREADS / 2; s > 0; s >>= 1) {
        if (tid < s) {
#pragma unroll
            for (int d = 0; d < DD; d++) red[tid * DD + d] += red[(tid + s) * DD + d];
        }
        __syncthreads();
    }
    if (tid < DD) g_part[blockIdx.x * DD + tid] = red[tid];
}

// ---------------- compound = mean(xs + sum P); h = relu(comp@Wat^T+bat) ------
__global__ void k_comp(int buf, const float* __restrict__ Wat, const float* __restrict__ bat) {
    __shared__ float red[512 * DD];
    int tid = threadIdx.x;
    float acc[DD];
#pragma unroll
    for (int d = 0; d < DD; d++) acc[d] = 0.f;
    const float* xs = g_xs[buf];
    for (int n = tid; n < N_ATOMS; n += 512) {
#pragma unroll
        for (int d = 0; d < DD; d++) {
            float v = xs[n * DD + d];
#pragma unroll
            for (int kb = 0; kb < KSPLIT; kb++) v += g_pp[kb][n * DD + d];
            acc[d] += v;
        }
    }
#pragma unroll
    for (int d = 0; d < DD; d++) red[tid * DD + d] = acc[d];
    __syncthreads();
    for (int s = 256; s > 0; s >>= 1) {
        if (tid < s) {
#pragma unroll
            for (int d = 0; d < DD; d++) red[tid * DD + d] += red[(tid + s) * DD + d];
        }
        __syncthreads();
    }
    if (tid < DD) {
        float comp = red[tid] * (1.f / N_ATOMS);
        g_comp[tid] = comp;
        float hv = bat[tid];
#pragma unroll
        for (int c = 0; c < DD; c++) hv = fmaf(red[c] * (1.f / N_ATOMS), Wat[tid * DD + c], hv);
        g_hatt[tid] = fmaxf(hv, 0.f);
    }
}

// ---------------- final: reduce g_part (512 blocks) + fusion MLP --------------
__global__ void k_final(const float* __restrict__ Wout, const float* __restrict__ bout,
                        const float* __restrict__ Wint, const float* __restrict__ bint,
                        float* __restrict__ out) {
    __shared__ float red[512 * DD];
    __shared__ float cat[20];
    int tid = threadIdx.x;
#pragma unroll
    for (int d = 0; d < DD; d++) red[tid * DD + d] = g_part[tid * DD + d];
    __syncthreads();
    for (int s = 256; s > 0; s >>= 1) {
        if (tid < s) {
#pragma unroll
            for (int d = 0; d < DD; d++) red[tid * DD + d] += red[(tid + s) * DD + d];
        }
        __syncthreads();
    }
    if (tid < DD) cat[tid] = g_comp[tid];
    if (tid >= DD && tid < 20) cat[tid] = red[tid - DD] * (1.f / L_WORDS);
    __syncthreads();
    if (tid < 32) {
        for (int j = 0; j < 3; j++) {
            float v = 0.f;
            if (tid < 20) {
                v = bout[j * 20 + tid];
                for (int c = 0; c < 20; c++) v = fmaf(cat[c], Wout[j * 400 + tid * 20 + c], v);
                v = fmaxf(v, 0.f);
            }
            __syncwarp();
            if (tid < 20) cat[tid] = v;
            __syncwarp();
        }
        if (tid < 2) {
            float v = bint[tid];
            for (int c = 0; c < 20; c++) v = fmaf(cat[c], Wint[tid * 20 + c], v);
            out[tid] = v;
        }
    }
}

// ---------------- launch ------------------------------------------------------
extern "C" void kernel_launch(void* const* d_in, const int* in_sizes, int n_in,
                              void* d_out, int out_size) {
    const int*   fp    = (const int*)d_in[0];
    const float* A     = (const float*)d_in[1];
    const int*   words = (const int*)d_in[2];
    const float* embf  = (const float*)d_in[3];
    const float* embw  = (const float*)d_in[4];
    const float* Wg    = (const float*)d_in[5];
    const float* bg    = (const float*)d_in[6];
    const float* Wc    = (const float*)d_in[7];
    const float* bc    = (const float*)d_in[8];
    const float* Wat   = (const float*)d_in[9];
    const float* bat   = (const float*)d_in[10];
    const float* Wout  = (const float*)d_in[11];
    const float* bout  = (const float*)d_in[12];
    const float* Wint  = (const float*)d_in[13];
    const float* bint  = (const float*)d_in[14];
    float* out = (float*)d_out;

    const int smem = 20 * (KCHUNK / 4) * 8;  // 40KB
    cudaFuncSetAttribute(k_gnn, cudaFuncAttributeMaxDynamicSharedMemorySize, smem);

    k_gather_fp<<<(N_ATOMS * DD + 255) / 256, 256>>>(fp, embf);
    k_gather_w<<<(L_WORDS * DD + 255) / 256, 256>>>(words, embw);

    dim3 ggrid(N_ATOMS / 16, KSPLIT);
    k_hs<<<N_ATOMS / 256, 256>>>(0, 0, 0, Wg + 0 * 100, bg + 0 * 10);
    k_gnn<<<ggrid, 256, smem>>>(A);
    k_hs<<<N_ATOMS / 256, 256>>>(0, 1, 1, Wg + 1 * 100, bg + 1 * 10);
    k_gnn<<<ggrid, 256, smem>>>(A);
    k_hs<<<N_ATOMS / 256, 256>>>(1, 0, 1, Wg + 2 * 100, bg + 2 * 10);
    k_gnn<<<ggrid, 256, smem>>>(A);
    k_comp<<<1, 512>>>(0, Wat, bat);     // xs3 = xs2 + sum(P) folded in; writes g_hatt

    k_cnn<<<L_WORDS / CTHREADS, CTHREADS>>>(0, Wc, bc, 0);   // buf0 -> buf1
    k_cnn<<<L_WORDS / CTHREADS, CTHREADS>>>(1, Wc, bc, 1);   // buf1 -> buf0
    k_cnn_att<<<L_WORDS / CTHREADS, CTHREADS>>>(0, Wc, bc, Wat, bat);  // fused

    k_final<<<1, 512>>>(Wout, bout, Wint, bint, out);
}

// round 5
// speedup vs baseline: 1.0849x; 1.0849x over previous
#include <cuda_runtime.h>
#include <cstdint>

#define N_ATOMS 4096
#define L_WORDS 65536
#define DD 10
#define KS 23
#define KSPLIT 2
#define KCHUNK (N_ATOMS / KSPLIT)   // 2048
#define NT 256
#define SMEM_BYTES 81920            // 20 * (KCHUNK/4) * 8

typedef unsigned long long ull;

// ---------------- scratch (device globals; no allocation allowed) ----------
__device__ float g_xs[N_ATOMS * DD];                 // xs, updated in place
__device__ ull   g_hs[4 * 5 * (N_ATOMS / 4)];        // hs f32x2, [k4][p][m/4]
__device__ float g_pp[KSPLIT][N_ATOMS * DD];         // split-K partials
__device__ float g_cnn[2][L_WORDS * DD];             // CNN ping-pong
__device__ float g_comp[DD];
__device__ float g_hatt[DD];
__device__ float g_part[256 * DD];                   // attention tile partials
__device__ float g_cpart[16 * DD];                   // compound partials
__device__ unsigned g_bar;                            // monotonic barrier counter

// ---------------- f32x2 helpers ----------------------------------------------
__device__ __forceinline__ ull pack2(float x, float y) {
    ull r; asm("mov.b64 %0, {%1, %2};" : "=l"(r) : "f"(x), "f"(y)); return r;
}
__device__ __forceinline__ void unpack2(ull v, float& x, float& y) {
    asm("mov.b64 {%0, %1}, %2;" : "=f"(x), "=f"(y) : "l"(v));
}
__device__ __forceinline__ void fma2(ull& d, ull a, ull b) {
    asm("fma.rn.f32x2 %0, %1, %2, %0;" : "+l"(d) : "l"(a), "l"(b));
}

// ---------------- grid barrier (monotonic; replay-safe) ----------------------
__device__ __forceinline__ void gbar() {
    __syncthreads();
    if (threadIdx.x == 0) {
        __threadfence();                       // release (CCTL.IVALL on gpu scope)
        unsigned old = atomicAdd(&g_bar, 1u);
        unsigned target = (old / gridDim.x + 1u) * gridDim.x;
        while (*(volatile unsigned*)&g_bar < target) { }
    }
    __syncthreads();
    __threadfence();                           // acquire: invalidate stale L1
}

// ================== the one persistent kernel =================================
__global__ void __launch_bounds__(NT) k_all(
    const int* __restrict__ fp, const float* __restrict__ A,
    const int* __restrict__ words, const float* __restrict__ embf,
    const float* __restrict__ embw,
    const float* __restrict__ Wg, const float* __restrict__ bg,
    const float* __restrict__ Wc, const float* __restrict__ bc,
    const float* __restrict__ Wat, const float* __restrict__ bat,
    const float* __restrict__ Wout, const float* __restrict__ bout,
    const float* __restrict__ Wint, const float* __restrict__ bint,
    float* __restrict__ out)
{
    extern __shared__ char smem_raw[];
    const int tid = threadIdx.x;
    const int bid = blockIdx.x;
    const int nb  = gridDim.x;
    const int gstride = nb * NT;

    // ---------- phase 0: gathers ----------
    for (int i = bid * NT + tid; i < N_ATOMS * DD; i += gstride) {
        int n = i / DD, d = i - n * DD;
        g_xs[i] = embf[(size_t)fp[n] * DD + d];
    }
    for (int i = bid * NT + tid; i < L_WORDS * DD; i += gstride) {
        int n = i / DD, d = i - n * DD;
        g_cnn[0][i] = embw[(size_t)words[n] * DD + d];
    }
    gbar();

    // ---------- GNN: 3 layers ----------
    for (int layer = 0; layer < 3; layer++) {
        const float* Wgl = Wg + layer * DD * DD;
        const float* bgl = bg + layer * DD;
        // hs phase: (combine partials for layer>0) + hs = relu(xs@W^T+b)
        for (int m = bid * NT + tid; m < N_ATOMS; m += gstride) {
            float x[DD];
#pragma unroll
            for (int c = 0; c < DD; c++) {
                float v = g_xs[m * DD + c];
                if (layer > 0) {
                    v += g_pp[0][m * DD + c] + g_pp[1][m * DD + c];
                    g_xs[m * DD + c] = v;
                }
                x[c] = v;
            }
            int k4 = m & 3, base = m >> 2;
#pragma unroll
            for (int p = 0; p < 5; p++) {
                float h0 = bgl[2 * p], h1 = bgl[2 * p + 1];
#pragma unroll
                for (int c = 0; c < DD; c++) {
                    h0 = fmaf(x[c], Wgl[(2 * p) * DD + c], h0);
                    h1 = fmaf(x[c], Wgl[(2 * p + 1) * DD + c], h1);
                }
                g_hs[(k4 * 5 + p) * (N_ATOMS / 4) + base] =
                    pack2(fmaxf(h0, 0.f), fmaxf(h1, 0.f));
            }
        }
        gbar();

        // mv phase: 256 tiles (128 row-blocks x 2 kb); warp owns 4 rows
        for (int t = bid; t < 128 * KSPLIT; t += nb) {
            int rowblk = t & 127, kb = t >> 7;
            ull* sh = (ull*)smem_raw;   // 20 * 512 ull = 80KB
            for (int i = tid; i < 20 * (KCHUNK / 4); i += NT) {
                int kp = i / (KCHUNK / 4), j = i % (KCHUNK / 4);
                sh[i] = g_hs[kp * (N_ATOMS / 4) + kb * (KCHUNK / 4) + j];
            }
            __syncthreads();

            int warp = tid >> 5, lane = tid & 31;
            int row0 = rowblk * 32 + warp * 4;
            float* pout = g_pp[kb];

            const float4* A4[4];
#pragma unroll
            for (int r = 0; r < 4; r++)
                A4[r] = (const float4*)(A + (size_t)(row0 + r) * N_ATOMS) + kb * (KCHUNK / 4);

            ull acc[4][5];
#pragma unroll
            for (int r = 0; r < 4; r++)
#pragma unroll
                for (int p = 0; p < 5; p++) acc[r][p] = 0ull;

            float4 a[4];
#pragma unroll
            for (int r = 0; r < 4; r++) a[r] = A4[r][lane];

            for (int it = 0; it < KCHUNK / 128; it++) {
                int q0 = it * 32;
                float4 nxt[4];
                if (it + 1 < KCHUNK / 128) {
#pragma unroll
                    for (int r = 0; r < 4; r++) nxt[r] = A4[r][q0 + 32 + lane];
                }
#pragma unroll
                for (int k = 0; k < 4; k++) {
                    ull h[5];
#pragma unroll
                    for (int p = 0; p < 5; p++)
                        h[p] = sh[(k * 5 + p) * (KCHUNK / 4) + q0 + lane];
                    float av0 = (k == 0) ? a[0].x : (k == 1) ? a[0].y : (k == 2) ? a[0].z : a[0].w;
                    float av1 = (k == 0) ? a[1].x : (k == 1) ? a[1].y : (k == 2) ? a[1].z : a[1].w;
                    float av2 = (k == 0) ? a[2].x : (k == 1) ? a[2].y : (k == 2) ? a[2].z : a[2].w;
                    float av3 = (k == 0) ? a[3].x : (k == 1) ? a[3].y : (k == 2) ? a[3].z : a[3].w;
                    ull v0 = pack2(av0, av0), v1 = pack2(av1, av1);
                    ull v2 = pack2(av2, av2), v3 = pack2(av3, av3);
#pragma unroll
                    for (int p = 0; p < 5; p++) {
                        fma2(acc[0][p], v0, h[p]);
                        fma2(acc[1][p], v1, h[p]);
                        fma2(acc[2][p], v2, h[p]);
                        fma2(acc[3][p], v3, h[p]);
                    }
                }
#pragma unroll
                for (int r = 0; r < 4; r++) a[r] = nxt[r];
            }

            float f[4][DD];
#pragma unroll
            for (int r = 0; r < 4; r++)
#pragma unroll
                for (int p = 0; p < 5; p++) unpack2(acc[r][p], f[r][2 * p], f[r][2 * p + 1]);
#pragma unroll
            for (int r = 0; r < 4; r++)
#pragma unroll
                for (int d = 0; d < DD; d++)
#pragma unroll
                    for (int o = 16; o > 0; o >>= 1)
                        f[r][d] += __shfl_down_sync(0xffffffffu, f[r][d], o);
            if (lane == 0) {
#pragma unroll
                for (int r = 0; r < 4; r++)
#pragma unroll
                    for (int d = 0; d < DD; d++)
                        pout[(row0 + r) * DD + d] = f[r][d];
            }
            __syncthreads();  // protect smem before next tile's fill
        }
        gbar();
    }

    // ---------- compound partials: 16 blocks x 256 atoms ----------
    {
        float* red = (float*)smem_raw;  // 256*10 floats
        for (int t = bid; t < 16; t += nb) {
            int n = t * 256 + tid;
            float acc[DD];
#pragma unroll
            for (int d = 0; d < DD; d++)
                acc[d] = g_xs[n * DD + d] + g_pp[0][n * DD + d] + g_pp[1][n * DD + d];
#pragma unroll
            for (int d = 0; d < DD; d++) red[tid * DD + d] = acc[d];
            __syncthreads();
            for (int s = 128; s > 0; s >>= 1) {
                if (tid < s) {
#pragma unroll
                    for (int d = 0; d < DD; d++) red[tid * DD + d] += red[(tid + s) * DD + d];
                }
                __syncthreads();
            }
            if (tid < DD) g_cpart[t * DD + tid] = red[tid];
            __syncthreads();
        }
    }
    gbar();

    // ---------- compound finalize (block 0) ----------
    if (bid == 0) {
        __shared__ float scomp[DD];
        if (tid < DD) {
            float s = 0.f;
            for (int i = 0; i < 16; i++) s += g_cpart[i * DD + tid];
            scomp[tid] = s * (1.f / N_ATOMS);
        }
        __syncthreads();
        if (tid < DD) {
            g_comp[tid] = scomp[tid];
            float hv = bat[tid];
#pragma unroll
            for (int c = 0; c < DD; c++) hv = fmaf(scomp[c], Wat[tid * DD + c], hv);
            g_hatt[tid] = fmaxf(hv, 0.f);
        }
    }
    gbar();

    // ---------- CNN: 3 layers (layer 2 fused with attention) ----------
    for (int layer = 0; layer < 3; layer++) {
        float* sIn = (float*)smem_raw;                       // (256+22)*11 floats
        ull*   sW  = (ull*)(smem_raw + ((NT + 22) * 11 * 4 + 7) / 8 * 8);  // 23*50 ull
        float* sWat = (float*)((char*)sW + KS * 50 * 8);     // 100 floats
        float* sbv  = sWat + DD * DD;                        // DD
        float* shv  = sbv + DD;                              // DD
        float* red  = shv + DD;                              // 256*10 floats
        const float* in  = g_cnn[layer & 1];
        float*       o   = g_cnn[(layer & 1) ^ 1];
        const float* W   = Wc + layer * KS * KS;
        const float  bias = bc[layer];
        const bool fuse = (layer == 2);

        for (int t = bid; t < L_WORDS / NT; t += nb) {
            for (int i = tid; i < KS * 50; i += NT) {
                int dl = i / 50, rem = i % 50, c = rem / 5, p = rem % 5;
                sW[i] = pack2(W[dl * KS + 11 + c - 2 * p],
                              W[dl * KS + 11 + c - 2 * p - 1]);
            }
            if (fuse) {
                if (tid < DD * DD) sWat[tid] = Wat[tid];
                if (tid < DD) { sbv[tid] = bat[tid]; shv[tid] = g_hatt[tid]; }
            }
            int base = t * NT - 11;
            for (int i = tid; i < (NT + 22) * DD; i += NT) {
                int rr = i / DD, c = i - rr * DD;
                int g = base + rr;
                sIn[rr * 11 + c] = (g >= 0 && g < L_WORDS) ? in[g * DD + c] : 0.f;
            }
            __syncthreads();

            ull b2 = pack2(bias, bias);
            ull acc[5];
#pragma unroll
            for (int p = 0; p < 5; p++) acc[p] = b2;
#pragma unroll 1
            for (int dl = 0; dl < KS; dl++) {
#pragma unroll
                for (int c = 0; c < DD; c++) {
                    float xv = sIn[(tid + dl) * 11 + c];
                    ull x2 = pack2(xv, xv);
#pragma unroll
                    for (int p = 0; p < 5; p++) fma2(acc[p], x2, sW[dl * 50 + c * 5 + p]);
                }
            }
            float x[DD];
#pragma unroll
            for (int p = 0; p < 5; p++) {
                float v0, v1;
                unpack2(acc[p], v0, v1);
                x[2 * p] = fmaxf(v0, 0.f);
                x[2 * p + 1] = fmaxf(v1, 0.f);
            }

            if (!fuse) {
                int grow = t * NT + tid;
#pragma unroll
                for (int d = 0; d < DD; d++) o[grow * DD + d] = x[d];
                __syncthreads();
            } else {
                float hp[DD], wl = 0.f;
#pragma unroll
                for (int u = 0; u < DD; u++) {
                    float v = sbv[u];
#pragma unroll
                    for (int c = 0; c < DD; c++) v = fmaf(x[c], sWat[u * DD + c], v);
                    v = fmaxf(v, 0.f);
                    hp[u] = v;
                    wl = fmaf(shv[u], v, wl);
                }
                wl = tanhf(wl);
#pragma unroll
                for (int d = 0; d < DD; d++) red[tid * DD + d] = wl * hp[d];
                __syncthreads();
                for (int s = 128; s > 0; s >>= 1) {
                    if (tid < s) {
#pragma unroll
                        for (int d = 0; d < DD; d++)
                            red[tid * DD + d] += red[(tid + s) * DD + d];
                    }
                    __syncthreads();
                }
                if (tid < DD) g_part[t * DD + tid] = red[tid];
                __syncthreads();
            }
        }
        gbar();
    }

    // ---------- final: reduce g_part (256 tiles) + fusion MLP (block 0) ------
    if (bid == 0) {
        float* red = (float*)smem_raw;   // 256*10
        float* cat = red + NT * DD;      // 20
#pragma unroll
        for (int d = 0; d < DD; d++) red[tid * DD + d] = g_part[tid * DD + d];
        __syncthreads();
        for (int s = 128; s > 0; s >>= 1) {
            if (tid < s) {
#pragma unroll
                for (int d = 0; d < DD; d++) red[tid * DD + d] += red[(tid + s) * DD + d];
            }
            __syncthreads();
        }
        if (tid < DD) cat[tid] = g_comp[tid];
        if (tid >= DD && tid < 20) cat[tid] = red[tid - DD] * (1.f / L_WORDS);
        __syncthreads();
        if (tid < 32) {
            for (int j = 0; j < 3; j++) {
                float v = 0.f;
                if (tid < 20) {
                    v = bout[j * 20 + tid];
                    for (int c = 0; c < 20; c++)
                        v = fmaf(cat[c], Wout[j * 400 + tid * 20 + c], v);
                    v = fmaxf(v, 0.f);
                }
                __syncwarp();
                if (tid < 20) cat[tid] = v;
                __syncwarp();
            }
            if (tid < 2) {
                float v = bint[tid];
                for (int c = 0; c < 20; c++) v = fmaf(cat[c], Wint[tid * 20 + c], v);
                out[tid] = v;
            }
        }
    }
}

// ---------------- launch ------------------------------------------------------
extern "C" void kernel_launch(void* const* d_in, const int* in_sizes, int n_in,
                              void* d_out, int out_size) {
    const int*   fp    = (const int*)d_in[0];
    const float* A     = (const float*)d_in[1];
    const int*   words = (const int*)d_in[2];
    const float* embf  = (const float*)d_in[3];
    const float* embw  = (const float*)d_in[4];
    const float* Wg    = (const float*)d_in[5];
    const float* bg    = (const float*)d_in[6];
    const float* Wc    = (const float*)d_in[7];
    const float* bc    = (const float*)d_in[8];
    const float* Wat   = (const float*)d_in[9];
    const float* bat   = (const float*)d_in[10];
    const float* Wout  = (const float*)d_in[11];
    const float* bout  = (const float*)d_in[12];
    const float* Wint  = (const float*)d_in[13];
    const float* bint  = (const float*)d_in[14];
    float* out = (float*)d_out;

    cudaFuncSetAttribute(k_all, cudaFuncAttributeMaxDynamicSharedMemorySize, SMEM_BYTES);
    int dev = 0;
    cudaGetDevice(&dev);
    int nsm = 0;
    cudaDeviceGetAttribute(&nsm, cudaDevAttrMultiProcessorCount, dev);
    int per = 0;
    cudaOccupancyMaxActiveBlocksPerMultiprocessor(&per, k_all, NT, SMEM_BYTES);
    if (per < 1) per = 1;
    if (per > 2) per = 2;
    int grid = nsm * per;   // all blocks guaranteed co-resident

    k_all<<<grid, NT, SMEM_BYTES>>>(fp, A, words, embf, embw, Wg, bg, Wc, bc,
                                    Wat, bat, Wout, bout, Wint, bint, out);
}

// round 6
// speedup vs baseline: 1.3214x; 1.2179x over previous
#include <cuda_runtime.h>
#include <cstdint>

#define N_ATOMS 4096
#define L_WORDS 65536
#define DD 10
#define KS 23
#define KSPLIT 2
#define KCHUNK (N_ATOMS / KSPLIT)   // 2048
#define NT 256
#define SMEM_BYTES 81920            // 40 * (KCHUNK/8) * 8 = 80KB

typedef unsigned long long ull;

// ---------------- scratch (device globals; no allocation allowed) ----------
__device__ float g_xs[N_ATOMS * DD];                 // xs, updated in place
__device__ ull   g_hs[8 * 5 * (N_ATOMS / 8)];        // hs f32x2, [k8][p][m/8]
__device__ uint4 g_Ab[(size_t)N_ATOMS * N_ATOMS / 8];// A in bf16 (8 cols / uint4)
__device__ float g_pp[KSPLIT][N_ATOMS * DD];         // split-K partials
__device__ float g_cnn[2][L_WORDS * DD];             // CNN ping-pong
__device__ float g_comp[DD];
__device__ float g_hatt[DD];
__device__ float g_part[256 * DD];                   // attention tile partials
__device__ float g_cpart[16 * DD];                   // compound partials
__device__ unsigned g_bar;                           // monotonic barrier counter

// ---------------- helpers ------------------------------------------------------
__device__ __forceinline__ ull pack2(float x, float y) {
    ull r; asm("mov.b64 %0, {%1, %2};" : "=l"(r) : "f"(x), "f"(y)); return r;
}
__device__ __forceinline__ void unpack2(ull v, float& x, float& y) {
    asm("mov.b64 {%0, %1}, %2;" : "=f"(x), "=f"(y) : "l"(v));
}
__device__ __forceinline__ void fma2(ull& d, ull a, ull b) {
    asm("fma.rn.f32x2 %0, %1, %2, %0;" : "+l"(d) : "l"(a), "l"(b));
}
__device__ __forceinline__ unsigned bfpack(float lo, float hi) {
    unsigned r;
    asm("cvt.rn.bf16x2.f32 %0, %1, %2;" : "=r"(r) : "f"(hi), "f"(lo));
    return r;
}

// ---------------- grid barrier (monotonic; replay-safe; gpu-fence = CCTL.IVALL)
__device__ __forceinline__ void gbar() {
    __syncthreads();
    if (threadIdx.x == 0) {
        __threadfence();
        unsigned old = atomicAdd(&g_bar, 1u);
        unsigned target = (old / gridDim.x + 1u) * gridDim.x;
        while (*(volatile unsigned*)&g_bar < target) { }
    }
    __syncthreads();
    __threadfence();
}

// ---------------- GNN mv tile: P[kb](rows) += A_bf16[rows, chunk] @ hs[chunk] --
__device__ __forceinline__ void mv_tile(char* smem_raw, int u) {
    ull* sh = (ull*)smem_raw;   // 40 * 256 ull = 80KB
    const int tid = threadIdx.x;
    const int rowblk = u & 127, kb = u >> 7;
    for (int i = tid; i < 40 * (KCHUNK / 8); i += NT) {
        int kp = i / (KCHUNK / 8), j = i % (KCHUNK / 8);
        sh[i] = g_hs[kp * (N_ATOMS / 8) + kb * (KCHUNK / 8) + j];
    }
    __syncthreads();

    const int warp = tid >> 5, lane = tid & 31;
    const int row0 = rowblk * 32 + warp * 4;
    float* pout = g_pp[kb];

    const uint4* Ab[4];
#pragma unroll
    for (int r = 0; r < 4; r++)
        Ab[r] = g_Ab + (size_t)(row0 + r) * (N_ATOMS / 8) + kb * (KCHUNK / 8);

    ull acc[4][5];
#pragma unroll
    for (int r = 0; r < 4; r++)
#pragma unroll
        for (int p = 0; p < 5; p++) acc[r][p] = 0ull;

    uint4 a[4];
#pragma unroll
    for (int r = 0; r < 4; r++) a[r] = Ab[r][lane];

    for (int it = 0; it < KCHUNK / 256; it++) {   // 8 iters x 256 cols
        int q0 = it * 32;
        uint4 nxt[4];
        if (it + 1 < KCHUNK / 256) {
#pragma unroll
            for (int r = 0; r < 4; r++) nxt[r] = Ab[r][q0 + 32 + lane];
        }
#pragma unroll
        for (int k8 = 0; k8 < 8; k8++) {
            ull h[5];
#pragma unroll
            for (int p = 0; p < 5; p++)
                h[p] = sh[(k8 * 5 + p) * (KCHUNK / 8) + q0 + lane];
#pragma unroll
            for (int r = 0; r < 4; r++) {
                unsigned w = (k8 < 2) ? a[r].x : (k8 < 4) ? a[r].y : (k8 < 6) ? a[r].z : a[r].w;
                float av = (k8 & 1) ? __uint_as_float(w & 0xffff0000u)
                                    : __uint_as_float(w << 16);
                ull v = pack2(av, av);
#pragma unroll
                for (int p = 0; p < 5; p++) fma2(acc[r][p], v, h[p]);
            }
        }
#pragma unroll
        for (int r = 0; r < 4; r++) a[r] = nxt[r];
    }

    float f[4][DD];
#pragma unroll
    for (int r = 0; r < 4; r++)
#pragma unroll
        for (int p = 0; p < 5; p++) unpack2(acc[r][p], f[r][2 * p], f[r][2 * p + 1]);
#pragma unroll
    for (int r = 0; r < 4; r++)
#pragma unroll
        for (int d = 0; d < DD; d++)
#pragma unroll
            for (int o = 16; o > 0; o >>= 1)
                f[r][d] += __shfl_down_sync(0xffffffffu, f[r][d], o);
    if ((tid & 31) == 0) {
#pragma unroll
        for (int r = 0; r < 4; r++)
#pragma unroll
            for (int d = 0; d < DD; d++)
                pout[(row0 + r) * DD + d] = f[r][d];
    }
}

// ---------------- CNN tile (plain layers 0,1): 256 rows -----------------------
__device__ __forceinline__ void cnn_tile(char* smem_raw, int t, int layer,
                                         const float* Wc, const float* bc) {
    float* sIn = (float*)smem_raw;                              // (256+22)*11
    ull*   sW  = (ull*)(smem_raw + 12288);                      // 23*50 ull
    const int tid = threadIdx.x;
    const float* in = g_cnn[layer & 1];
    float*       o  = g_cnn[(layer & 1) ^ 1];
    const float* W  = Wc + layer * KS * KS;
    const float bias = bc[layer];

    for (int i = tid; i < KS * 50; i += NT) {
        int dl = i / 50, rem = i % 50, c = rem / 5, p = rem % 5;
        sW[i] = pack2(W[dl * KS + 11 + c - 2 * p], W[dl * KS + 11 + c - 2 * p - 1]);
    }
    int base = t * NT - 11;
    for (int i = tid; i < (NT + 22) * DD; i += NT) {
        int rr = i / DD, c = i - rr * DD;
        int g = base + rr;
        sIn[rr * 11 + c] = (g >= 0 && g < L_WORDS) ? in[g * DD + c] : 0.f;
    }
    __syncthreads();

    ull b2 = pack2(bias, bias);
    ull acc[5];
#pragma unroll
    for (int p = 0; p < 5; p++) acc[p] = b2;
#pragma unroll 1
    for (int dl = 0; dl < KS; dl++) {
#pragma unroll
        for (int c = 0; c < DD; c++) {
            float xv = sIn[(tid + dl) * 11 + c];
            ull x2 = pack2(xv, xv);
#pragma unroll
            for (int p = 0; p < 5; p++) fma2(acc[p], x2, sW[dl * 50 + c * 5 + p]);
        }
    }
    int grow = t * NT + tid;
#pragma unroll
    for (int p = 0; p < 5; p++) {
        float v0, v1;
        unpack2(acc[p], v0, v1);
        o[grow * DD + 2 * p]     = fmaxf(v0, 0.f);
        o[grow * DD + 2 * p + 1] = fmaxf(v1, 0.f);
    }
}

// ---------------- CNN layer2 fused with attention ------------------------------
__device__ __forceinline__ void cnn_att_tile(char* smem_raw, int t,
                                             const float* Wc, const float* bc,
                                             const float* Wat, const float* bat) {
    float* sIn  = (float*)smem_raw;
    ull*   sW   = (ull*)(smem_raw + 12288);
    float* sWat = (float*)(smem_raw + 12288 + KS * 50 * 8);
    float* sbv  = sWat + DD * DD;
    float* shv  = sbv + DD;
    float* red  = shv + DD + 2;
    const int tid = threadIdx.x;
    const float* in = g_cnn[0];
    const float* W  = Wc + 2 * KS * KS;
    const float bias = bc[2];

    for (int i = tid; i < KS * 50; i += NT) {
        int dl = i / 50, rem = i % 50, c = rem / 5, p = rem % 5;
        sW[i] = pack2(W[dl * KS + 11 + c - 2 * p], W[dl * KS + 11 + c - 2 * p - 1]);
    }
    if (tid < DD * DD) sWat[tid] = Wat[tid];
    if (tid < DD) { sbv[tid] = bat[tid]; shv[tid] = g_hatt[tid]; }
    int base = t * NT - 11;
    for (int i = tid; i < (NT + 22) * DD; i += NT) {
        int rr = i / DD, c = i - rr * DD;
        int g = base + rr;
        sIn[rr * 11 + c] = (g >= 0 && g < L_WORDS) ? in[g * DD + c] : 0.f;
    }
    __syncthreads();

    ull b2 = pack2(bias, bias);
    ull acc[5];
#pragma unroll
    for (int p = 0; p < 5; p++) acc[p] = b2;
#pragma unroll 1
    for (int dl = 0; dl < KS; dl++) {
#pragma unroll
        for (int c = 0; c < DD; c++) {
            float xv = sIn[(tid + dl) * 11 + c];
            ull x2 = pack2(xv, xv);
#pragma unroll
            for (int p = 0; p < 5; p++) fma2(acc[p], x2, sW[dl * 50 + c * 5 + p]);
        }
    }
    float x[DD];
#pragma unroll
    for (int p = 0; p < 5; p++) {
        float v0, v1;
        unpack2(acc[p], v0, v1);
        x[2 * p] = fmaxf(v0, 0.f);
        x[2 * p + 1] = fmaxf(v1, 0.f);
    }
    float hp[DD], wl = 0.f;
#pragma unroll
    for (int u = 0; u < DD; u++) {
        float v = sbv[u];
#pragma unroll
        for (int c = 0; c < DD; c++) v = fmaf(x[c], sWat[u * DD + c], v);
        v = fmaxf(v, 0.f);
        hp[u] = v;
        wl = fmaf(shv[u], v, wl);
    }
    wl = tanhf(wl);
#pragma unroll
    for (int d = 0; d < DD; d++) red[tid * DD + d] = wl * hp[d];
    __syncthreads();
    for (int s = 128; s > 0; s >>= 1) {
        if (tid < s) {
#pragma unroll
            for (int d = 0; d < DD; d++) red[tid * DD + d] += red[(tid + s) * DD + d];
        }
        __syncthreads();
    }
    if (tid < DD) g_part[t * DD + tid] = red[tid];
}

// ================== the one persistent kernel =================================
__global__ void __launch_bounds__(NT, 2) k_all(
    const int* __restrict__ fp, const float* __restrict__ A,
    const int* __restrict__ words, const float* __restrict__ embf,
    const float* __restrict__ embw,
    const float* __restrict__ Wg, const float* __restrict__ bg,
    const float* __restrict__ Wc, const float* __restrict__ bc,
    const float* __restrict__ Wat, const float* __restrict__ bat,
    const float* __restrict__ Wout, const float* __restrict__ bout,
    const float* __restrict__ Wint, const float* __restrict__ bint,
    float* __restrict__ out)
{
    extern __shared__ char smem_raw[];
    const int tid = threadIdx.x;
    const int bid = blockIdx.x;
    const int nb  = gridDim.x;
    const int gstride = nb * NT;

    // ---------- P0: gathers + A -> bf16 conversion ----------
    for (int i = bid * NT + tid; i < N_ATOMS * DD; i += gstride) {
        int n = i / DD, d = i - n * DD;
        g_xs[i] = embf[(size_t)fp[n] * DD + d];
    }
    for (int i = bid * NT + tid; i < L_WORDS * DD; i += gstride) {
        int n = i / DD, d = i - n * DD;
        g_cnn[0][i] = embw[(size_t)words[n] * DD + d];
    }
    {
        const float4* Af = (const float4*)A;
        for (int v = bid * NT + tid; v < N_ATOMS * N_ATOMS / 8; v += gstride) {
            float4 x0 = Af[2 * v], x1 = Af[2 * v + 1];
            uint4 o;
            o.x = bfpack(x0.x, x0.y);
            o.y = bfpack(x0.z, x0.w);
            o.z = bfpack(x1.x, x1.y);
            o.w = bfpack(x1.z, x1.w);
            g_Ab[v] = o;
        }
    }
    gbar();

    // ---------- GNN layers (mv overlapped with CNN layers 0,1) ----------
    for (int layer = 0; layer < 3; layer++) {
        const float* Wgl = Wg + layer * DD * DD;
        const float* bgl = bg + layer * DD;
        // hs phase (+ xs update for layer>0)
        for (int m = bid * NT + tid; m < N_ATOMS; m += gstride) {
            float x[DD];
#pragma unroll
            for (int c = 0; c < DD; c++) {
                float v = g_xs[m * DD + c];
                if (layer > 0) {
                    v += g_pp[0][m * DD + c] + g_pp[1][m * DD + c];
                    g_xs[m * DD + c] = v;
                }
                x[c] = v;
            }
            int k8 = m & 7, base = m >> 3;
#pragma unroll
            for (int p = 0; p < 5; p++) {
                float h0 = bgl[2 * p], h1 = bgl[2 * p + 1];
#pragma unroll
                for (int c = 0; c < DD; c++) {
                    h0 = fmaf(x[c], Wgl[(2 * p) * DD + c], h0);
                    h1 = fmaf(x[c], Wgl[(2 * p + 1) * DD + c], h1);
                }
                g_hs[(k8 * 5 + p) * (N_ATOMS / 8) + base] =
                    pack2(fmaxf(h0, 0.f), fmaxf(h1, 0.f));
            }
        }
        gbar();

        // mv tiles (256) + cnn tiles (256, layers 0/1 only)
        int units = (layer < 2) ? 512 : 256;
        for (int u = bid; u < units; u += nb) {
            if (u < 256) mv_tile(smem_raw, u);
            else cnn_tile(smem_raw, u - 256, layer, Wc, bc);
            __syncthreads();
        }
        gbar();
    }

    // ---------- compound partials: 16 tiles ----------
    {
        float* red = (float*)smem_raw;
        for (int t = bid; t < 16; t += nb) {
            int n = t * 256 + tid;
            float acc[DD];
#pragma unroll
            for (int d = 0; d < DD; d++)
                acc[d] = g_xs[n * DD + d] + g_pp[0][n * DD + d] + g_pp[1][n * DD + d];
#pragma unroll
            for (int d = 0; d < DD; d++) red[tid * DD + d] = acc[d];
            __syncthreads();
            for (int s = 128; s > 0; s >>= 1) {
                if (tid < s) {
#pragma unroll
                    for (int d = 0; d < DD; d++)
                        red[tid * DD + d] += red[(tid + s) * DD + d];
                }
                __syncthreads();
            }
            if (tid < DD) g_cpart[t * DD + tid] = red[tid];
            __syncthreads();
        }
    }
    gbar();

    // ---------- compound finalize (block 0) ----------
    if (bid == 0) {
        __shared__ float scomp[DD];
        if (tid < DD) {
            float s = 0.f;
            for (int i = 0; i < 16; i++) s += g_cpart[i * DD + tid];
            scomp[tid] = s * (1.f / N_ATOMS);
        }
        __syncthreads();
        if (tid < DD) {
            g_comp[tid] = scomp[tid];
            float hv = bat[tid];
#pragma unroll
            for (int c = 0; c < DD; c++) hv = fmaf(scomp[c], Wat[tid * DD + c], hv);
            g_hatt[tid] = fmaxf(hv, 0.f);
        }
    }
    gbar();

    // ---------- CNN layer 2 fused with attention: 256 tiles ----------
    for (int t = bid; t < 256; t += nb) {
        cnn_att_tile(smem_raw, t, Wc, bc, Wat, bat);
        __syncthreads();
    }
    gbar();

    // ---------- final: reduce g_part + fusion MLP (block 0) ----------
    if (bid == 0) {
        float* red = (float*)smem_raw;
        float* cat = red + NT * DD;
#pragma unroll
        for (int d = 0; d < DD; d++) red[tid * DD + d] = g_part[tid * DD + d];
        __syncthreads();
        for (int s = 128; s > 0; s >>= 1) {
            if (tid < s) {
#pragma unroll
                for (int d = 0; d < DD; d++) red[tid * DD + d] += red[(tid + s) * DD + d];
            }
            __syncthreads();
        }
        if (tid < DD) cat[tid] = g_comp[tid];
        if (tid >= DD && tid < 20) cat[tid] = red[tid - DD] * (1.f / L_WORDS);
        __syncthreads();
        if (tid < 32) {
            for (int j = 0; j < 3; j++) {
                float v = 0.f;
                if (tid < 20) {
                    v = bout[j * 20 + tid];
                    for (int c = 0; c < 20; c++)
                        v = fmaf(cat[c], Wout[j * 400 + tid * 20 + c], v);
                    v = fmaxf(v, 0.f);
                }
                __syncwarp();
                if (tid < 20) cat[tid] = v;
                __syncwarp();
            }
            if (tid < 2) {
                float v = bint[tid];
                for (int c = 0; c < 20; c++) v = fmaf(cat[c], Wint[tid * 20 + c], v);
                out[tid] = v;
            }
        }
    }
}

// ---------------- launch ------------------------------------------------------
extern "C" void kernel_launch(void* const* d_in, const int* in_sizes, int n_in,
                              void* d_out, int out_size) {
    const int*   fp    = (const int*)d_in[0];
    const float* A     = (const float*)d_in[1];
    const int*   words = (const int*)d_in[2];
    const float* embf  = (const float*)d_in[3];
    const float* embw  = (const float*)d_in[4];
    const float* Wg    = (const float*)d_in[5];
    const float* bg    = (const float*)d_in[6];
    const float* Wc    = (const float*)d_in[7];
    const float* bc    = (const float*)d_in[8];
    const float* Wat   = (const float*)d_in[9];
    const float* bat   = (const float*)d_in[10];
    const float* Wout  = (const float*)d_in[11];
    const float* bout  = (const float*)d_in[12];
    const float* Wint  = (const float*)d_in[13];
    const float* bint  = (const float*)d_in[14];
    float* out = (float*)d_out;

    cudaFuncSetAttribute(k_all, cudaFuncAttributeMaxDynamicSharedMemorySize, SMEM_BYTES);
    int dev = 0;
    cudaGetDevice(&dev);
    int nsm = 0;
    cudaDeviceGetAttribute(&nsm, cudaDevAttrMultiProcessorCount, dev);
    int per = 0;
    cudaOccupancyMaxActiveBlocksPerMultiprocessor(&per, k_all, NT, SMEM_BYTES);
    if (per < 1) per = 1;
    if (per > 2) per = 2;
    int grid = nsm * per;   // all blocks guaranteed co-resident

    k_all<<<grid, NT, SMEM_BYTES>>>(fp, A, words, embf, embw, Wg, bg, Wc, bc,
                                    Wat, bat, Wout, bout, Wint, bint, out);
}